// round 15
// baseline (speedup 1.0000x reference)
#include <cuda_runtime.h>
#include <math.h>

#define BB 2
#define TT 1024
#define DD 128
#define HH 64
// DH = 2

// Scratch (allocation-free contract: __device__ globals)
__device__ float g_Qh[BB * HH * TT * 2];    // Q head-major: [(b*64+h)*1024+t] float2
__device__ float g_KV[BB * HH * TT * 4];    // (k0,k1,v0,v1) per (b,h,t)
__device__ float g_AO[BB * TT * DD];        // attention out, row-major [t_glob][d]

__device__ __forceinline__ float ex2f(float x) {
    float y;
    asm("ex2.approx.ftz.f32 %0, %1;" : "=f"(y) : "f"(x));
    return y;
}

// packed f32x2 helpers (sm_103a — only reachable via PTX)
__device__ __forceinline__ void ffma2(unsigned long long& d,
                                      unsigned long long a,
                                      unsigned long long b) {
    asm("fma.rn.f32x2 %0, %1, %2, %0;" : "+l"(d) : "l"(a), "l"(b));
}
__device__ __forceinline__ unsigned long long mul2(unsigned long long a,
                                                   unsigned long long b) {
    unsigned long long d;
    asm("mul.rn.f32x2 %0, %1, %2;" : "=l"(d) : "l"(a), "l"(b));
    return d;
}
__device__ __forceinline__ void fma2acc(unsigned long long& d,
                                        unsigned long long a,
                                        unsigned long long b,
                                        unsigned long long c) {
    asm("fma.rn.f32x2 %0, %1, %2, %3;" : "=l"(d) : "l"(a), "l"(b), "l"(c));
}
__device__ __forceinline__ void add2(unsigned long long& d, unsigned long long a) {
    asm("add.rn.f32x2 %0, %0, %1;" : "+l"(d) : "l"(a));
}
__device__ __forceinline__ unsigned long long pack2(float v) {
    unsigned long long r;
    asm("mov.b64 %0, {%1, %1};" : "=l"(r) : "f"(v));
    return r;
}
__device__ __forceinline__ unsigned long long packf2(float a, float b) {
    unsigned long long r;
    asm("mov.b64 %0, {%1, %2};" : "=l"(r) : "f"(a), "f"(b));
    return r;
}
__device__ __forceinline__ float2 unpack2(unsigned long long v) {
    float2 f;
    asm("mov.b64 {%0, %1}, %2;" : "=f"(f.x), "=f"(f.y) : "l"(v));
    return f;
}

// ---------------------------------------------------------------------------
// GEMM core: 32 rows x 64 cols per block, full K=128 weight slab.
// Weight staged DIRECTLY from the untransposed W (row-major 128x128):
//   sW[k][c] = W[col0+c][k]
// Thread (c = tid&63, kq = tid>>6) owns one 128B line of row col0+c
// (k-band kq*32..kq*32+31): 8 float4 LDG (1 miss + 7 L1 hits) and 32
// conflict-free scalar STS (consecutive c across lanes).
// Compute (proven round-9 loop): warp w -> rows 4w..4w+3, lane owns 2 cols,
// per k: 1 LDS.64 + 4 broadcast LDS + 4 pack + 4 FFMA2.
// ---------------------------------------------------------------------------
__device__ __forceinline__ void gemm32x64(const float* __restrict__ A,
                                          const float* __restrict__ W,
                                          int row0, int col0,
                                          float sX[32][DD],
                                          float sW[DD][64],
                                          unsigned long long acc[4]) {
    const int tid = threadIdx.x;
    const int warp = tid >> 5;
    const int lane = tid & 31;

    // Stage 32 A rows: 1024 float4, coalesced
    #pragma unroll
    for (int i = 0; i < 4; i++) {
        const int idx = tid + i * 256;
        reinterpret_cast<float4*>(&sX[0][0])[idx] =
            reinterpret_cast<const float4*>(A + row0 * DD)[idx];
    }
    // Transposing weight stage: sW[k][c] = W[col0+c][k]
    {
        const int c = tid & 63;
        const int kq = tid >> 6;              // 0..3 -> k-band kq*32..kq*32+31
        const float* __restrict__ wrow = W + (col0 + c) * DD;
        #pragma unroll
        for (int i = 0; i < 8; i++) {
            const int k4 = (kq * 8 + i) * 4;  // 4-aligned k within band
            const float4 w = *reinterpret_cast<const float4*>(wrow + k4);
            sW[k4 + 0][c] = w.x;
            sW[k4 + 1][c] = w.y;
            sW[k4 + 2][c] = w.z;
            sW[k4 + 3][c] = w.w;
        }
    }
    __syncthreads();

    const int r0 = warp * 4;
    const int c2 = lane * 2;
    acc[0] = acc[1] = acc[2] = acc[3] = 0ull;

    #pragma unroll 8
    for (int k = 0; k < DD; k++) {
        const unsigned long long wv =
            *reinterpret_cast<const unsigned long long*>(&sW[k][c2]);
        ffma2(acc[0], pack2(sX[r0 + 0][k]), wv);
        ffma2(acc[1], pack2(sX[r0 + 1][k]), wv);
        ffma2(acc[2], pack2(sX[r0 + 2][k]), wv);
        ffma2(acc[3], pack2(sX[r0 + 3][k]), wv);
    }
}

// ---------------------------------------------------------------------------
// QKV projection: grid (64, 2, 3), 256 threads. No transpose pre-pass needed.
// Lane's col pair = one head's (d0,d1). Writes head-major Q / interleaved KV.
// ---------------------------------------------------------------------------
__global__ void __launch_bounds__(256) qkv_kernel(const float* __restrict__ x,
                                                  const float* __restrict__ Wq,
                                                  const float* __restrict__ Wk,
                                                  const float* __restrict__ Wv) {
    __shared__ float sX[32][DD];   // 16 KB
    __shared__ float sW[DD][64];   // 32 KB  (48 KB total)

    const int row0 = blockIdx.x * 32;
    const int col0 = blockIdx.y * 64;
    const int z = blockIdx.z;                 // 0=Q, 1=K, 2=V
    const float* W = (z == 0) ? Wq : (z == 1) ? Wk : Wv;

    unsigned long long acc[4];
    gemm32x64(x, W, row0, col0, sX, sW, acc);

    const int warp = threadIdx.x >> 5;
    const int lane = threadIdx.x & 31;
    const int h = (col0 >> 1) + lane;         // head index 0..63

    float2* __restrict__ Qp  = reinterpret_cast<float2*>(g_Qh);
    float2* __restrict__ KVp = reinterpret_cast<float2*>(g_KV);

    #pragma unroll
    for (int i = 0; i < 4; i++) {
        const int rg = row0 + warp * 4 + i;
        const int b = rg >> 10;
        const int t0 = rg & 1023;
        const int idx = (b * HH + h) * TT + t0;
        const float2 f = unpack2(acc[i]);
        if (z == 0)      Qp[idx] = f;
        else if (z == 1) KVp[idx * 2] = f;        // K -> .xy
        else             KVp[idx * 2 + 1] = f;    // V -> .zw
    }
}

// ---------------------------------------------------------------------------
// Causal attention, DH=2. One block per (b,h), 512 threads.
// Thread tid owns queries {tid, 1023-tid} (1025 keys -> balanced).
// Single-pass softmax (no max subtraction; scores bounded, rescale exact).
// Packed f32x2 inner loop: 2 keys per iter via pair-major K/V smem layout.
// ---------------------------------------------------------------------------
__global__ void __launch_bounds__(512) attn_kernel() {
    __shared__ float4 sKp[TT / 2];   // 8 KB
    __shared__ float4 sVp[TT / 2];   // 8 KB

    const int tid = threadIdx.x;
    const int bh = blockIdx.x;                // b*64 + h
    const int b = bh >> 6;
    const int h = bh & 63;

    const float4* __restrict__ KVp = reinterpret_cast<const float4*>(g_KV) + bh * TT;
    const float2* __restrict__ Qp  = reinterpret_cast<const float2*>(g_Qh) + bh * TT;

    // Pair-major staging: thread handles key pair (2*tid, 2*tid+1)
    {
        const float4 a = KVp[2 * tid];
        const float4 c = KVp[2 * tid + 1];
        sKp[tid] = make_float4(a.x, c.x, a.y, c.y);
        sVp[tid] = make_float4(a.z, c.z, a.w, c.w);
    }
    __syncthreads();

    // fold 1/(sqrt(DH)*temperature) and log2(e) into the query
    const float cf = 1.4426950408889634f / (1.4142135623730951f * 0.8f);
    float2* __restrict__ Op = reinterpret_cast<float2*>(g_AO);

    #pragma unroll
    for (int qi = 0; qi < 2; qi++) {
        const int q = qi ? (TT - 1 - tid) : tid;
        const float2 qv = Qp[q];
        const float q0 = qv.x * cf;
        const float q1 = qv.y * cf;
        const unsigned long long q0p = pack2(q0);
        const unsigned long long q1p = pack2(q1);

        const int npairs = (q + 1) >> 1;
        unsigned long long lp = 0ull, o0p = 0ull, o1p = 0ull;

        #pragma unroll 4
        for (int m = 0; m < npairs; m++) {
            const ulonglong2 kk = *reinterpret_cast<const ulonglong2*>(&sKp[m]);
            unsigned long long s01;
            fma2acc(s01, q1p, kk.y, mul2(q0p, kk.x));
            const float2 s = unpack2(s01);
            const unsigned long long p01 = packf2(ex2f(s.x), ex2f(s.y));
            const ulonglong2 vv = *reinterpret_cast<const ulonglong2*>(&sVp[m]);
            add2(lp, p01);
            ffma2(o0p, p01, vv.x);
            ffma2(o1p, p01, vv.y);
        }

        const float2 lf = unpack2(lp);
        const float2 o0f = unpack2(o0p);
        const float2 o1f = unpack2(o1p);
        float l = lf.x + lf.y;
        float o0 = o0f.x + o0f.y;
        float o1 = o1f.x + o1f.y;

        if (((q + 1) & 1) != 0) {            // q even: scalar tail for key q
            const float4 kk = sKp[q >> 1];
            const float4 vv = sVp[q >> 1];
            const float s = fmaf(q1, kk.z, q0 * kk.x);
            const float p = ex2f(s);
            l += p;
            o0 = fmaf(p, vv.x, o0);
            o1 = fmaf(p, vv.z, o1);
        }

        const float inv = 1.0f / l;
        Op[(b * TT + q) * HH + h] = make_float2(o0 * inv, o1 * inv);
    }
}

// ---------------------------------------------------------------------------
// Output projection: out = AO @ Wo^T, Wo staged+transposed directly. grid (64,2).
// ---------------------------------------------------------------------------
__global__ void __launch_bounds__(256) proj_kernel(const float* __restrict__ Wo,
                                                   float* __restrict__ out) {
    __shared__ float sX[32][DD];   // 16 KB
    __shared__ float sW[DD][64];   // 32 KB

    const int row0 = blockIdx.x * 32;
    const int col0 = blockIdx.y * 64;

    unsigned long long acc[4];
    gemm32x64(g_AO, Wo, row0, col0, sX, sW, acc);

    const int warp = threadIdx.x >> 5;
    const int lane = threadIdx.x & 31;

    #pragma unroll
    for (int i = 0; i < 4; i++) {
        const int rg = row0 + warp * 4 + i;
        const float2 f = unpack2(acc[i]);
        *reinterpret_cast<float2*>(out + rg * DD + col0 + lane * 2) = f;
    }
}

extern "C" void kernel_launch(void* const* d_in, const int* in_sizes, int n_in,
                              void* d_out, int out_size) {
    const float* x  = (const float*)d_in[0];
    const float* Wq = (const float*)d_in[1];
    const float* Wk = (const float*)d_in[2];
    const float* Wv = (const float*)d_in[3];
    const float* Wo = (const float*)d_in[4];
    float* out = (float*)d_out;

    qkv_kernel<<<dim3(64, 2, 3), 256>>>(x, Wq, Wk, Wv);
    attn_kernel<<<BB * HH, 512>>>();
    proj_kernel<<<dim3(64, 2), 256>>>(Wo, out);
}

// round 17
// speedup vs baseline: 1.0506x; 1.0506x over previous
#include <cuda_runtime.h>
#include <math.h>

#define BB 2
#define TT 1024
#define DD 128
#define HH 64
// DH = 2

// Scratch (allocation-free contract: __device__ globals)
__device__ float g_Qh[BB * HH * TT * 2];    // Q head-major: [(b*64+h)*1024+t] float2
__device__ float g_KV[BB * HH * TT * 4];    // (k0,k1,v0,v1) per (b,h,t)
__device__ float g_AO[BB * TT * DD];        // attention out, row-major [t_glob][d]

__device__ __forceinline__ float ex2f(float x) {
    float y;
    asm("ex2.approx.ftz.f32 %0, %1;" : "=f"(y) : "f"(x));
    return y;
}

// packed f32x2 helpers (sm_103a — only reachable via PTX)
__device__ __forceinline__ void ffma2(unsigned long long& d,
                                      unsigned long long a,
                                      unsigned long long b) {
    asm("fma.rn.f32x2 %0, %1, %2, %0;" : "+l"(d) : "l"(a), "l"(b));
}
__device__ __forceinline__ unsigned long long mul2(unsigned long long a,
                                                   unsigned long long b) {
    unsigned long long d;
    asm("mul.rn.f32x2 %0, %1, %2;" : "=l"(d) : "l"(a), "l"(b));
    return d;
}
__device__ __forceinline__ void fma2acc(unsigned long long& d,
                                        unsigned long long a,
                                        unsigned long long b,
                                        unsigned long long c) {
    asm("fma.rn.f32x2 %0, %1, %2, %3;" : "=l"(d) : "l"(a), "l"(b), "l"(c));
}
__device__ __forceinline__ void add2(unsigned long long& d, unsigned long long a) {
    asm("add.rn.f32x2 %0, %0, %1;" : "+l"(d) : "l"(a));
}
__device__ __forceinline__ unsigned long long pack2(float v) {
    unsigned long long r;
    asm("mov.b64 %0, {%1, %1};" : "=l"(r) : "f"(v));
    return r;
}
__device__ __forceinline__ unsigned long long packf2(float a, float b) {
    unsigned long long r;
    asm("mov.b64 %0, {%1, %2};" : "=l"(r) : "f"(a), "f"(b));
    return r;
}
__device__ __forceinline__ float2 unpack2(unsigned long long v) {
    float2 f;
    asm("mov.b64 {%0, %1}, %2;" : "=f"(f.x), "=f"(f.y) : "l"(v));
    return f;
}

// ---------------------------------------------------------------------------
// Z-fused QKV projection (the proven mega-kernel phase-1, standalone).
// grid (64, 2) = 128 blocks x 512 threads, 80 KB dynamic smem:
//   sX  [32][128]  16 KB  at float offset 0      (x rows, staged once)
//   sW0 [128][64]  32 KB  at float offset 4096   (double-buffered slabs)
//   sW1 [128][64]  32 KB  at float offset 12288
// Warps 0-7 compute slab z (4 rows/warp, lane owns 2 cols, f32x2 FMA);
// warps 8-15 transpose-stage slab z+1 (sW[k][c] = W[col0+c][k]).
// Exposed staging: 1 slab (z=0) instead of 3.
// ---------------------------------------------------------------------------
extern __shared__ float qsmem[];

__global__ void __launch_bounds__(512) qkv_kernel(const float* __restrict__ x,
                                                  const float* __restrict__ Wq,
                                                  const float* __restrict__ Wk,
                                                  const float* __restrict__ Wv) {
    const int tid = threadIdx.x;
    const int warp = tid >> 5;
    const int lane = tid & 31;

    const int row0 = blockIdx.x * 32;
    const int col0 = blockIdx.y * 64;

    float (*sX)[DD]  = reinterpret_cast<float(*)[DD]>(qsmem);
    float (*sW0)[64] = reinterpret_cast<float(*)[64]>(qsmem + 4096);
    float (*sW1)[64] = reinterpret_cast<float(*)[64]>(qsmem + 12288);

    // Stage 32 x rows (1024 float4, 2/thread) — once for all three z's
    #pragma unroll
    for (int i = 0; i < 2; i++) {
        const int idx = tid + i * 512;
        reinterpret_cast<float4*>(&sX[0][0])[idx] =
            reinterpret_cast<const float4*>(x + row0 * DD)[idx];
    }
    // Stage slab 0 (Wq) with all 512 threads, transposing:
    // thread (c = tid&63, kq8 = tid>>6 in 0..7) stages 16 k's of row col0+c.
    {
        const int c = tid & 63;
        const int kq = tid >> 6;              // 0..7 -> k-band of 16
        const float* __restrict__ wrow = Wq + (col0 + c) * DD;
        #pragma unroll
        for (int i = 0; i < 4; i++) {
            const int k4 = (kq * 4 + i) * 4;
            const float4 w = *reinterpret_cast<const float4*>(wrow + k4);
            sW0[k4 + 0][c] = w.x;
            sW0[k4 + 1][c] = w.y;
            sW0[k4 + 2][c] = w.z;
            sW0[k4 + 3][c] = w.w;
        }
    }
    __syncthreads();

    float2* __restrict__ Qp  = reinterpret_cast<float2*>(g_Qh);
    float2* __restrict__ KVp = reinterpret_cast<float2*>(g_KV);

    #pragma unroll
    for (int z = 0; z < 3; z++) {
        float (*cur)[64] = (z & 1) ? sW1 : sW0;
        if (warp < 8) {
            // ---- compute slab z: 4 rows/warp, lane owns cols c2, c2+1 ----
            const int r0 = warp * 4;
            const int c2 = lane * 2;
            unsigned long long acc[4] = {0ull, 0ull, 0ull, 0ull};
            #pragma unroll 8
            for (int k = 0; k < DD; k++) {
                const unsigned long long wv =
                    *reinterpret_cast<const unsigned long long*>(&cur[k][c2]);
                ffma2(acc[0], pack2(sX[r0 + 0][k]), wv);
                ffma2(acc[1], pack2(sX[r0 + 1][k]), wv);
                ffma2(acc[2], pack2(sX[r0 + 2][k]), wv);
                ffma2(acc[3], pack2(sX[r0 + 3][k]), wv);
            }
            const int h = (col0 >> 1) + lane;   // lane's col pair = head h
            #pragma unroll
            for (int i = 0; i < 4; i++) {
                const int rg = row0 + r0 + i;
                const int b = rg >> 10;
                const int t0 = rg & 1023;
                const int idx = (b * HH + h) * TT + t0;
                const float2 f = unpack2(acc[i]);
                if (z == 0)      Qp[idx] = f;
                else if (z == 1) KVp[idx * 2] = f;        // K -> .xy
                else             KVp[idx * 2 + 1] = f;    // V -> .zw
            }
        } else if (z < 2) {
            // ---- stage slab z+1 with warps 8-15 (256 threads) ----
            float (*nxt)[64] = (z & 1) ? sW0 : sW1;
            const float* __restrict__ Wn = (z == 0) ? Wk : Wv;
            const int st = tid - 256;
            const int c = st & 63;
            const int kq = st >> 6;           // 0..3 -> k-band of 32
            const float* __restrict__ wrow = Wn + (col0 + c) * DD;
            #pragma unroll
            for (int i = 0; i < 8; i++) {
                const int k4 = (kq * 8 + i) * 4;
                const float4 w = *reinterpret_cast<const float4*>(wrow + k4);
                nxt[k4 + 0][c] = w.x;
                nxt[k4 + 1][c] = w.y;
                nxt[k4 + 2][c] = w.z;
                nxt[k4 + 3][c] = w.w;
            }
        }
        __syncthreads();
    }
}

// ---------------------------------------------------------------------------
// Causal attention, DH=2. One block per (b,h), 512 threads.  (round-15 proven)
// Thread tid owns queries {tid, 1023-tid} (1025 keys -> balanced).
// Single-pass softmax (no max subtraction; scores bounded, rescale exact).
// Packed f32x2 inner loop: 2 keys per iter via pair-major K/V smem layout.
// ---------------------------------------------------------------------------
__global__ void __launch_bounds__(512) attn_kernel() {
    __shared__ float4 sKp[TT / 2];   // 8 KB
    __shared__ float4 sVp[TT / 2];   // 8 KB

    const int tid = threadIdx.x;
    const int bh = blockIdx.x;                // b*64 + h
    const int b = bh >> 6;
    const int h = bh & 63;

    const float4* __restrict__ KVp = reinterpret_cast<const float4*>(g_KV) + bh * TT;
    const float2* __restrict__ Qp  = reinterpret_cast<const float2*>(g_Qh) + bh * TT;

    // Pair-major staging: thread handles key pair (2*tid, 2*tid+1)
    {
        const float4 a = KVp[2 * tid];
        const float4 c = KVp[2 * tid + 1];
        sKp[tid] = make_float4(a.x, c.x, a.y, c.y);
        sVp[tid] = make_float4(a.z, c.z, a.w, c.w);
    }
    __syncthreads();

    // fold 1/(sqrt(DH)*temperature) and log2(e) into the query
    const float cf = 1.4426950408889634f / (1.4142135623730951f * 0.8f);
    float2* __restrict__ Op = reinterpret_cast<float2*>(g_AO);

    #pragma unroll
    for (int qi = 0; qi < 2; qi++) {
        const int q = qi ? (TT - 1 - tid) : tid;
        const float2 qv = Qp[q];
        const float q0 = qv.x * cf;
        const float q1 = qv.y * cf;
        const unsigned long long q0p = pack2(q0);
        const unsigned long long q1p = pack2(q1);

        const int npairs = (q + 1) >> 1;
        unsigned long long lp = 0ull, o0p = 0ull, o1p = 0ull;

        #pragma unroll 4
        for (int m = 0; m < npairs; m++) {
            const ulonglong2 kk = *reinterpret_cast<const ulonglong2*>(&sKp[m]);
            unsigned long long s01;
            fma2acc(s01, q1p, kk.y, mul2(q0p, kk.x));
            const float2 s = unpack2(s01);
            const unsigned long long p01 = packf2(ex2f(s.x), ex2f(s.y));
            const ulonglong2 vv = *reinterpret_cast<const ulonglong2*>(&sVp[m]);
            add2(lp, p01);
            ffma2(o0p, p01, vv.x);
            ffma2(o1p, p01, vv.y);
        }

        const float2 lf = unpack2(lp);
        const float2 o0f = unpack2(o0p);
        const float2 o1f = unpack2(o1p);
        float l = lf.x + lf.y;
        float o0 = o0f.x + o0f.y;
        float o1 = o1f.x + o1f.y;

        if (((q + 1) & 1) != 0) {            // q even: scalar tail for key q
            const float4 kk = sKp[q >> 1];
            const float4 vv = sVp[q >> 1];
            const float s = fmaf(q1, kk.z, q0 * kk.x);
            const float p = ex2f(s);
            l += p;
            o0 = fmaf(p, vv.x, o0);
            o1 = fmaf(p, vv.z, o1);
        }

        const float inv = 1.0f / l;
        Op[(b * TT + q) * HH + h] = make_float2(o0 * inv, o1 * inv);
    }
}

// ---------------------------------------------------------------------------
// Output projection: out = AO @ Wo^T, transposing weight stage. (round-15 proven)
// grid (64, 2), 256 threads, 48 KB static smem.
// ---------------------------------------------------------------------------
__global__ void __launch_bounds__(256) proj_kernel(const float* __restrict__ Wo,
                                                   float* __restrict__ out) {
    __shared__ float sX[32][DD];   // 16 KB
    __shared__ float sW[DD][64];   // 32 KB

    const int tid = threadIdx.x;
    const int warp = tid >> 5;
    const int lane = tid & 31;
    const int row0 = blockIdx.x * 32;
    const int col0 = blockIdx.y * 64;

    // Stage 32 AO rows
    #pragma unroll
    for (int i = 0; i < 4; i++) {
        const int idx = tid + i * 256;
        reinterpret_cast<float4*>(&sX[0][0])[idx] =
            reinterpret_cast<const float4*>(g_AO + row0 * DD)[idx];
    }
    // Transposing weight stage: sW[k][c] = Wo[col0+c][k]
    {
        const int c = tid & 63;
        const int kq = tid >> 6;              // 0..3 -> k-band of 32
        const float* __restrict__ wrow = Wo + (col0 + c) * DD;
        #pragma unroll
        for (int i = 0; i < 8; i++) {
            const int k4 = (kq * 8 + i) * 4;
            const float4 w = *reinterpret_cast<const float4*>(wrow + k4);
            sW[k4 + 0][c] = w.x;
            sW[k4 + 1][c] = w.y;
            sW[k4 + 2][c] = w.z;
            sW[k4 + 3][c] = w.w;
        }
    }
    __syncthreads();

    const int r0 = warp * 4;
    const int c2 = lane * 2;
    unsigned long long acc[4] = {0ull, 0ull, 0ull, 0ull};

    #pragma unroll 8
    for (int k = 0; k < DD; k++) {
        const unsigned long long wv =
            *reinterpret_cast<const unsigned long long*>(&sW[k][c2]);
        ffma2(acc[0], pack2(sX[r0 + 0][k]), wv);
        ffma2(acc[1], pack2(sX[r0 + 1][k]), wv);
        ffma2(acc[2], pack2(sX[r0 + 2][k]), wv);
        ffma2(acc[3], pack2(sX[r0 + 3][k]), wv);
    }

    #pragma unroll
    for (int i = 0; i < 4; i++) {
        const int rg = row0 + r0 + i;
        const float2 f = unpack2(acc[i]);
        *reinterpret_cast<float2*>(out + rg * DD + col0 + c2) = f;
    }
}

extern "C" void kernel_launch(void* const* d_in, const int* in_sizes, int n_in,
                              void* d_out, int out_size) {
    const float* x  = (const float*)d_in[0];
    const float* Wq = (const float*)d_in[1];
    const float* Wk = (const float*)d_in[2];
    const float* Wv = (const float*)d_in[3];
    const float* Wo = (const float*)d_in[4];
    float* out = (float*)d_out;

    cudaFuncSetAttribute(qkv_kernel, cudaFuncAttributeMaxDynamicSharedMemorySize,
                         80 * 1024);
    qkv_kernel<<<dim3(64, 2), 512, 80 * 1024>>>(x, Wq, Wk, Wv);
    attn_kernel<<<BB * HH, 512>>>();
    proj_kernel<<<dim3(64, 2), 256>>>(Wo, out);
}